// round 8
// baseline (speedup 1.0000x reference)
#include <cuda_runtime.h>
#include <cuda_fp16.h>
#include <math.h>
#include <stdint.h>

#define BDIM 4
#define LSEQ 8192
#define HDIM 256
#define PDIM 256
#define MROWS (BDIM * LSEQ)      // 32768
#define NPLANES 1024             // interleaved: n = dir*512 + 2*p + (re/im)

// ---------------- scratch (no allocations allowed) ----------------
__device__ __half g_x16[(size_t)MROWS * HDIM];          // 16MB
__device__ __half g_W1[(size_t)NPLANES * HDIM];         // 0.5MB [n][h], n interleaved
__device__ __half g_W2[(size_t)HDIM * NPLANES];         // 0.5MB [h][n], n interleaved
__device__ float g_Lbar[2][2][PDIM];
__device__ __half g_Bu[(size_t)MROWS * NPLANES];        // 64MB fp16, interleaved cols
__device__ __half g_Xs[(size_t)MROWS * NPLANES];        // 64MB fp16, interleaved cols

// ---------------- PTX helpers ----------------
__device__ __forceinline__ uint32_t smem_u32(const void* p) {
    uint32_t a;
    asm("{ .reg .u64 t; cvta.to.shared.u64 t, %1; cvt.u32.u64 %0, t; }" : "=r"(a) : "l"(p));
    return a;
}
__device__ __forceinline__ void cp16(uint32_t dst, const void* src) {
    asm volatile("cp.async.cg.shared.global [%0], [%1], 16;" :: "r"(dst), "l"(src) : "memory");
}
__device__ __forceinline__ void cp_commit() { asm volatile("cp.async.commit_group;" ::: "memory"); }
template<int N> __device__ __forceinline__ void cp_wait() { asm volatile("cp.async.wait_group %0;" :: "n"(N) : "memory"); }

__device__ __forceinline__ void ldmx4(uint32_t* r, uint32_t addr) {
    asm volatile("ldmatrix.sync.aligned.m8n8.x4.shared.b16 {%0,%1,%2,%3}, [%4];"
                 : "=r"(r[0]), "=r"(r[1]), "=r"(r[2]), "=r"(r[3]) : "r"(addr));
}
__device__ __forceinline__ void mma16816(float* d, const uint32_t* a, const uint32_t* b) {
    asm volatile("mma.sync.aligned.m16n8k16.row.col.f32.f16.f16.f32 "
                 "{%0,%1,%2,%3}, {%4,%5,%6,%7}, {%8,%9}, {%0,%1,%2,%3};"
                 : "+f"(d[0]), "+f"(d[1]), "+f"(d[2]), "+f"(d[3])
                 : "r"(a[0]), "r"(a[1]), "r"(a[2]), "r"(a[3]), "r"(b[0]), "r"(b[1]));
}

__device__ __forceinline__ float gelu_exact(float v) {
    return 0.5f * v * (1.0f + erff(v * 0.70710678118654752f));
}

// ---------------- discretize + pack W1 (fp16, interleaved rows) ----------------
__global__ void k_prep(const float* __restrict__ log_real,
                       const float* __restrict__ imag,
                       const float* __restrict__ log_Delta,
                       const float* __restrict__ Br,
                       const float* __restrict__ Bi,
                       int dir) {
    int p = blockIdx.x;
    int h = threadIdx.x;

    float Lr = -expf(log_real[p]);
    float Li = imag[p];
    float Delta = expf(log_Delta[p]);
    float ead = expf(Lr * Delta);
    float bd = Li * Delta;
    float Lbr = ead * cosf(bd);
    float Lbi = ead * sinf(bd);
    if (h == 0) {
        g_Lbar[dir][0][p] = Lbr;
        g_Lbar[dir][1][p] = Lbi;
    }
    float denom = fmaxf(Lr * Lr + Li * Li, 1e-12f);
    float ivr = Lr / denom;
    float ivi = -Li / denom;
    float dr = Lbr - 1.0f;
    float di = Lbi;
    float cr = ivr * dr - ivi * di;
    float ci = ivr * di + ivi * dr;

    float br = Br[p * HDIM + h];
    float bi = Bi[p * HDIM + h];
    float vr = cr * br - ci * bi;
    float vi = cr * bi + ci * br;

    g_W1[(size_t)(dir * 512 + 2 * p) * HDIM + h]     = __float2half_rn(vr);
    g_W1[(size_t)(dir * 512 + 2 * p + 1) * HDIM + h] = __float2half_rn(vi);
}

// ---------------- pack W2 (fp16, interleaved k) ----------------
__global__ void k_packW2(const float* __restrict__ Cfr, const float* __restrict__ Cfi,
                         const float* __restrict__ Cbr, const float* __restrict__ Cbi) {
    int h = blockIdx.x;
    int p = threadIdx.x;
    size_t rb = (size_t)h * NPLANES;
    g_W2[rb + 2 * p]           = __float2half_rn( Cfr[h * PDIM + p]);
    g_W2[rb + 2 * p + 1]       = __float2half_rn(-Cfi[h * PDIM + p]);
    g_W2[rb + 512 + 2 * p]     = __float2half_rn( Cbr[h * PDIM + p]);
    g_W2[rb + 512 + 2 * p + 1] = __float2half_rn(-Cbi[h * PDIM + p]);
}

// ---------------- x -> fp16 ----------------
__global__ void k_cvt_x(const float* __restrict__ x) {
    size_t i4 = (size_t)blockIdx.x * blockDim.x + threadIdx.x;
    size_t i = i4 * 4;
    float4 v = *(const float4*)(x + i);
    __half2* dst = (__half2*)(g_x16 + i);
    dst[0] = __halves2half2(__float2half_rn(v.x), __float2half_rn(v.y));
    dst[1] = __halves2half2(__float2half_rn(v.z), __float2half_rn(v.w));
}

// ---------------- GEMM1: 128x128 tile, 3-stage pipeline, fp16 out ----------------
#define PADB 80
#define A_TILE_B (128 * PADB)       // 10240
#define STAGE1_B (2 * A_TILE_B)     // A + B (both 128 rows)
#define GEMM1_SMEM (3 * STAGE1_B)   // 61440

__global__ void __launch_bounds__(256, 2)
k_gemm1(const __half* __restrict__ A, int lda,
        const __half* __restrict__ B, int ldb,
        __half* __restrict__ C, int ldc, int K) {
    extern __shared__ char smc[];
    uint32_t s0 = smem_u32(smc);
    int tid = threadIdx.x;
    int wid = tid >> 5, lane = tid & 31;
    int bx = blockIdx.x, by = blockIdx.y;

    const __half* pA = A + (size_t)(by * 128) * lda;
    const __half* pB = B + (size_t)(bx * 128) * ldb;

    int r0 = tid >> 2, c0 = tid & 3;
    int r1 = r0 + 64;
    auto load_stage = [&](int s, int k0) {
        uint32_t st = s0 + s * STAGE1_B;
        uint32_t so0 = r0 * PADB + c0 * 16;
        uint32_t so1 = r1 * PADB + c0 * 16;
        cp16(st + so0, pA + (size_t)r0 * lda + k0 + c0 * 8);
        cp16(st + so1, pA + (size_t)r1 * lda + k0 + c0 * 8);
        cp16(st + A_TILE_B + so0, pB + (size_t)r0 * ldb + k0 + c0 * 8);
        cp16(st + A_TILE_B + so1, pB + (size_t)r1 * ldb + k0 + c0 * 8);
        cp_commit();
    };

    int wm = (wid & 3) * 32;
    int wn = (wid >> 2) * 64;

    float acc[2][8][4];
#pragma unroll
    for (int i = 0; i < 2; i++)
#pragma unroll
        for (int j = 0; j < 8; j++)
#pragma unroll
            for (int q = 0; q < 4; q++) acc[i][j][q] = 0.0f;

    uint32_t a_row = (wm + (lane & 15)) * PADB;
    uint32_t a_col = (lane >> 4) * 16;
    int q = lane >> 3;
    uint32_t b_row = (wn + (q >> 1) * 8 + (lane & 7)) * PADB;
    uint32_t b_col = (q & 1) * 16;

    int nc = K / 32;
    load_stage(0, 0);
    if (nc > 1) load_stage(1, 32);

    for (int c = 0; c < nc; c++) {
        if (c + 2 < nc) { load_stage((c + 2) % 3, (c + 2) * 32); cp_wait<2>(); }
        else if (c + 1 < nc) { cp_wait<1>(); }
        else { cp_wait<0>(); }
        __syncthreads();

        uint32_t st = s0 + (c % 3) * STAGE1_B;
#pragma unroll
        for (int kk = 0; kk < 2; kk++) {
            uint32_t aF[2][4], bF[8][2];
#pragma unroll
            for (int i = 0; i < 2; i++)
                ldmx4(aF[i], st + a_row + i * (16 * PADB) + a_col + kk * 32);
#pragma unroll
            for (int j = 0; j < 4; j++) {
                uint32_t rh[4];
                ldmx4(rh, st + A_TILE_B + b_row + j * (16 * PADB) + b_col + kk * 32);
                bF[2 * j][0] = rh[0]; bF[2 * j][1] = rh[1];
                bF[2 * j + 1][0] = rh[2]; bF[2 * j + 1][1] = rh[3];
            }
#pragma unroll
            for (int i = 0; i < 2; i++)
#pragma unroll
                for (int j = 0; j < 8; j++)
                    mma16816(acc[i][j], aF[i], bF[j]);
        }
        __syncthreads();
    }

    int m0 = by * 128 + wm + (lane >> 2);
    int n0 = bx * 128 + wn + (lane & 3) * 2;
#pragma unroll
    for (int i = 0; i < 2; i++)
#pragma unroll
        for (int j = 0; j < 8; j++) {
            size_t r = (size_t)(m0 + i * 16) * ldc + n0 + j * 8;
            size_t r2 = r + 8 * (size_t)ldc;
            *(__half2*)(C + r)  = __halves2half2(__float2half_rn(acc[i][j][0]),
                                                 __float2half_rn(acc[i][j][1]));
            *(__half2*)(C + r2) = __halves2half2(__float2half_rn(acc[i][j][2]),
                                                 __float2half_rn(acc[i][j][3]));
        }
}

// ---------------- GEMM2 fused: dual pass (dir0 -> accF, dir1 -> accB) + epilogue ----------------
// CTA tile 128(m) x 64(n=h), warp tile 32x32, 8 warps. K=512 per pass. 3-stage pipeline.
#define A2_TILE_B (128 * PADB)              // 10240
#define B2_TILE_B (64 * PADB)               // 5120
#define STAGE2_B (A2_TILE_B + B2_TILE_B)    // 15360
#define GEMM2_SMEM (3 * STAGE2_B)           // 46080

__global__ void __launch_bounds__(256, 2)
k_gemm2_fused(const __half* __restrict__ Xs,   // [MROWS][NPLANES]
              const __half* __restrict__ W2,   // [HDIM][NPLANES]
              float* __restrict__ out,
              const __half* __restrict__ Xin,
              const float* __restrict__ Df, const float* __restrict__ Db) {
    extern __shared__ char smc[];
    uint32_t s0 = smem_u32(smc);
    int tid = threadIdx.x;
    int wid = tid >> 5, lane = tid & 31;
    int bx = blockIdx.x, by = blockIdx.y;

    int r0 = tid >> 2, c0 = tid & 3;     // A: rows r0, r0+64 (2 chunks); B: row r0 (1 chunk)
    int wm = (wid & 3) * 32;
    int wn = (wid >> 2) * 32;

    uint32_t a_row = (wm + (lane & 15)) * PADB;
    uint32_t a_col = (lane >> 4) * 16;
    int q = lane >> 3;
    uint32_t b_row = (wn + (q >> 1) * 8 + (lane & 7)) * PADB;
    uint32_t b_col = (q & 1) * 16;

    float accF[2][4][4], accB[2][4][4];
#pragma unroll
    for (int i = 0; i < 2; i++)
#pragma unroll
        for (int j = 0; j < 4; j++)
#pragma unroll
            for (int t = 0; t < 4; t++) { accF[i][j][t] = 0.0f; accB[i][j][t] = 0.0f; }

#pragma unroll
    for (int pass = 0; pass < 2; pass++) {
        const __half* pA = Xs + pass * 512 + (size_t)(by * 128) * NPLANES;
        const __half* pB = W2 + pass * 512 + (size_t)(bx * 64) * NPLANES;

        auto load_stage = [&](int s, int k0) {
            uint32_t st = s0 + s * STAGE2_B;
            uint32_t so0 = r0 * PADB + c0 * 16;
            uint32_t so1 = (r0 + 64) * PADB + c0 * 16;
            cp16(st + so0, pA + (size_t)r0 * NPLANES + k0 + c0 * 8);
            cp16(st + so1, pA + (size_t)(r0 + 64) * NPLANES + k0 + c0 * 8);
            if (r0 < 64)
                cp16(st + A2_TILE_B + so0, pB + (size_t)r0 * NPLANES + k0 + c0 * 8);
            cp_commit();
        };

        const int nc = 16;  // 512 / 32
        load_stage(0, 0);
        load_stage(1, 32);

        for (int c = 0; c < nc; c++) {
            if (c + 2 < nc) { load_stage((c + 2) % 3, (c + 2) * 32); cp_wait<2>(); }
            else if (c + 1 < nc) { cp_wait<1>(); }
            else { cp_wait<0>(); }
            __syncthreads();

            uint32_t st = s0 + (c % 3) * STAGE2_B;
#pragma unroll
            for (int kk = 0; kk < 2; kk++) {
                uint32_t aF[2][4], bF[4][2];
#pragma unroll
                for (int i = 0; i < 2; i++)
                    ldmx4(aF[i], st + a_row + i * (16 * PADB) + a_col + kk * 32);
#pragma unroll
                for (int j = 0; j < 2; j++) {
                    uint32_t rh[4];
                    ldmx4(rh, st + A2_TILE_B + b_row + j * (16 * PADB) + b_col + kk * 32);
                    bF[2 * j][0] = rh[0]; bF[2 * j][1] = rh[1];
                    bF[2 * j + 1][0] = rh[2]; bF[2 * j + 1][1] = rh[3];
                }
#pragma unroll
                for (int i = 0; i < 2; i++)
#pragma unroll
                    for (int j = 0; j < 4; j++) {
                        if (pass == 0) mma16816(accF[i][j], aF[i], bF[j]);
                        else           mma16816(accB[i][j], aF[i], bF[j]);
                    }
            }
            __syncthreads();
        }
    }

    // fused final epilogue
    int m0 = by * 128 + wm + (lane >> 2);
    int n0 = bx * 64 + wn + (lane & 3) * 2;
#pragma unroll
    for (int i = 0; i < 2; i++)
#pragma unroll
        for (int j = 0; j < 4; j++) {
            int n = n0 + j * 8;
            float2 df = *(const float2*)(Df + n);
            float2 db = *(const float2*)(Db + n);
            size_t r = (size_t)(m0 + i * 16) * HDIM + n;
            size_t r2 = r + 8 * (size_t)HDIM;
            float2 xv0 = __half22float2(*(const __half2*)(Xin + r));
            float2 xv1 = __half22float2(*(const __half2*)(Xin + r2));
            float2 o0, o1;
            o0.x = gelu_exact(fmaf(df.x, xv0.x, accF[i][j][0])) + gelu_exact(fmaf(db.x, xv0.x, accB[i][j][0]));
            o0.y = gelu_exact(fmaf(df.y, xv0.y, accF[i][j][1])) + gelu_exact(fmaf(db.y, xv0.y, accB[i][j][1]));
            o1.x = gelu_exact(fmaf(df.x, xv1.x, accF[i][j][2])) + gelu_exact(fmaf(db.x, xv1.x, accB[i][j][2]));
            o1.y = gelu_exact(fmaf(df.y, xv1.y, accF[i][j][3])) + gelu_exact(fmaf(db.y, xv1.y, accB[i][j][3]));
            *(float2*)(out + r)  = o0;
            *(float2*)(out + r2) = o1;
        }
}

// ---------------- chunked truncated scan (fp16 in/out, interleaved re/im) ----------------
#define CH 256
#define WU 64
__global__ void k_scan() {
    int p     = threadIdx.x;
    int blk   = blockIdx.x;
    int chunk = blk & 31;
    int dir   = (blk >> 5) & 1;
    int b     = blk >> 6;

    float Ar = g_Lbar[dir][0][p];
    float Ai = g_Lbar[dir][1][p];
    int s = chunk * CH;
    int e = s + CH;
    size_t rowBase = (size_t)b * LSEQ;
    int col = dir * 512 + 2 * p;

    float xr = 0.0f, xi = 0.0f;

    if (dir == 0) {
        int l0 = s - WU; if (l0 < 0) l0 = 0;
#pragma unroll 8
        for (int l = l0; l < s; ++l) {
            float2 u = __half22float2(*(const __half2*)(g_Bu + (rowBase + l) * NPLANES + col));
            float nr = fmaf(Ar, xr, fmaf(-Ai, xi, u.x));
            float ni = fmaf(Ar, xi, fmaf( Ai, xr, u.y));
            xr = nr; xi = ni;
        }
#pragma unroll 8
        for (int l = s; l < e; ++l) {
            size_t idx = (rowBase + l) * NPLANES + col;
            float2 u = __half22float2(*(const __half2*)(g_Bu + idx));
            float nr = fmaf(Ar, xr, fmaf(-Ai, xi, u.x));
            float ni = fmaf(Ar, xi, fmaf( Ai, xr, u.y));
            xr = nr; xi = ni;
            *(__half2*)(g_Xs + idx) = __halves2half2(__float2half_rn(xr), __float2half_rn(xi));
        }
    } else {
        int l1 = e + WU; if (l1 > LSEQ) l1 = LSEQ;
#pragma unroll 8
        for (int l = l1 - 1; l >= e; --l) {
            float2 u = __half22float2(*(const __half2*)(g_Bu + (rowBase + l) * NPLANES + col));
            float nr = fmaf(Ar, xr, fmaf(-Ai, xi, u.x));
            float ni = fmaf(Ar, xi, fmaf( Ai, xr, u.y));
            xr = nr; xi = ni;
        }
#pragma unroll 8
        for (int l = e - 1; l >= s; --l) {
            size_t idx = (rowBase + l) * NPLANES + col;
            float2 u = __half22float2(*(const __half2*)(g_Bu + idx));
            float nr = fmaf(Ar, xr, fmaf(-Ai, xi, u.x));
            float ni = fmaf(Ar, xi, fmaf( Ai, xr, u.y));
            xr = nr; xi = ni;
            *(__half2*)(g_Xs + idx) = __halves2half2(__float2half_rn(xr), __float2half_rn(xi));
        }
    }
}

// ---------------- launcher ----------------
extern "C" void kernel_launch(void* const* d_in, const int* in_sizes, int n_in,
                              void* d_out, int out_size) {
    const float* x = (const float*)d_in[0];

    static int smem_set = 0;
    if (!smem_set) {
        cudaFuncSetAttribute(k_gemm1, cudaFuncAttributeMaxDynamicSharedMemorySize, GEMM1_SMEM);
        cudaFuncSetAttribute(k_gemm2_fused, cudaFuncAttributeMaxDynamicSharedMemorySize, GEMM2_SMEM);
        smem_set = 1;
    }

    k_prep<<<256, 256>>>((const float*)d_in[1], (const float*)d_in[2], (const float*)d_in[3],
                         (const float*)d_in[4], (const float*)d_in[5], 0);
    k_prep<<<256, 256>>>((const float*)d_in[9], (const float*)d_in[10], (const float*)d_in[11],
                         (const float*)d_in[12], (const float*)d_in[13], 1);
    k_packW2<<<256, 256>>>((const float*)d_in[6], (const float*)d_in[7],
                           (const float*)d_in[14], (const float*)d_in[15]);
    k_cvt_x<<<8192, 256>>>(x);

    __half *px16, *pW1, *pW2, *pXs, *pBu;
    cudaGetSymbolAddress((void**)&px16, g_x16);
    cudaGetSymbolAddress((void**)&pW1,  g_W1);
    cudaGetSymbolAddress((void**)&pW2,  g_W2);
    cudaGetSymbolAddress((void**)&pXs,  g_Xs);
    cudaGetSymbolAddress((void**)&pBu,  g_Bu);

    // GEMM1: Bu[32768][1024](fp16) = x @ W1^T   (M=32768, N=1024, K=256)
    k_gemm1<<<dim3(8, 256), 256, GEMM1_SMEM>>>(px16, HDIM, pW1, HDIM, pBu, NPLANES, HDIM);

    // scans (both directions)
    k_scan<<<256, 256>>>();

    // GEMM2 fused: out = gelu(Yf + Df*x) + gelu(Yb + Db*x), Yf/Yb in registers
    k_gemm2_fused<<<dim3(4, 256), 256, GEMM2_SMEM>>>(pXs, pW2, (float*)d_out, px16,
                                                     (const float*)d_in[8], (const float*)d_in[16]);
}